// round 14
// baseline (speedup 1.0000x reference)
#include <cuda_runtime.h>
#include <cuda_bf16.h>

#define DD 128
#define NMAX 40000
#define KW 68    // packed k-word stride (bf16x2): bank = 4*gid+tig -> conflict-free frags

// ---------------- device scratch (no allocs allowed), 16B-aligned ----------------
__device__ __align__(16) float g_delta[(size_t)NMAX * 3];
__device__ __align__(16) float g_xf[(size_t)NMAX * DD];
__device__ __align__(16) float g_aggr[(size_t)NMAX * DD];
__device__ int   g_is64;

__device__ __forceinline__ float lrelu(float v) { return v >= 0.f ? v : 0.01f * v; }

__device__ __forceinline__ void red_add_v4(float* addr, float4 v) {
    asm volatile("red.global.add.v4.f32 [%0], {%1,%2,%3,%4};"
                 :: "l"(addr), "f"(v.x), "f"(v.y), "f"(v.z), "f"(v.w) : "memory");
}

// ---------------- bf16 helpers ----------------
// pack two floats as bf16x2: lo half = first arg (even k), hi half = second (odd k)
__device__ __forceinline__ unsigned pack_bf16(float lo, float hi) {
    unsigned r;
    asm("cvt.rn.bf16x2.f32 %0, %1, %2;" : "=r"(r) : "f"(hi), "f"(lo));
    return r;
}
__device__ __forceinline__ float bf16_round(float v) {
    return __bfloat162float(__float2bfloat16(v));   // rn
}
// split v into bf16-representable h (returned) and residual l (exact in fp32)
__device__ __forceinline__ float split_hi(float v, float& l) {
    float h = bf16_round(v);
    l = v - h;
    return h;
}

__device__ __forceinline__ void mma_bf16(float d[4], const unsigned a[4],
                                         unsigned b0, unsigned b1) {
    asm("mma.sync.aligned.m16n8k16.row.col.f32.bf16.bf16.f32 "
        "{%0,%1,%2,%3}, {%4,%5,%6,%7}, {%8,%9}, {%0,%1,%2,%3};"
        : "+f"(d[0]), "+f"(d[1]), "+f"(d[2]), "+f"(d[3])
        : "r"(a[0]), "r"(a[1]), "r"(a[2]), "r"(a[3]), "r"(b0), "r"(b1));
}

// Warp-tiled 3-pass bf16 GEMM: rows [rw,rw+32) x cols [cw,cw+32).
// Ah/Al: [64][KW] packed bf16x2 along k. Wh/Wl: [128 n][KW] packed bf16x2 along k (transposed).
// acc[m][j][r]: row = rw+16m+gid+8*(r>>1), col = cw+8j+2*tig+(r&1)
__device__ __forceinline__ void gemm_warp(const unsigned* __restrict__ Ah,
                                          const unsigned* __restrict__ Al,
                                          const unsigned* __restrict__ Wh,
                                          const unsigned* __restrict__ Wl,
                                          int rw, int cw, int lane,
                                          float acc[2][4][4]) {
    const int gid = lane >> 2, tig = lane & 3;
    #pragma unroll
    for (int m = 0; m < 2; m++)
        #pragma unroll
        for (int j = 0; j < 4; j++)
            #pragma unroll
            for (int r = 0; r < 4; r++) acc[m][j][r] = 0.f;

    #pragma unroll 2
    for (int kw = 0; kw < 64; kw += 8) {   // 8 words = 16 k per step
        unsigned ah[2][4], al[2][4];
        #pragma unroll
        for (int m = 0; m < 2; m++) {
            int base = (rw + 16 * m + gid) * KW + kw + tig;
            ah[m][0] = Ah[base];          ah[m][1] = Ah[base + 8 * KW];
            ah[m][2] = Ah[base + 4];      ah[m][3] = Ah[base + 8 * KW + 4];
            al[m][0] = Al[base];          al[m][1] = Al[base + 8 * KW];
            al[m][2] = Al[base + 4];      al[m][3] = Al[base + 8 * KW + 4];
        }
        #pragma unroll
        for (int j = 0; j < 4; j++) {
            int nb = (cw + 8 * j + gid) * KW + kw + tig;
            unsigned bh0 = Wh[nb], bh1 = Wh[nb + 4];
            unsigned bl0 = Wl[nb], bl1 = Wl[nb + 4];
            #pragma unroll
            for (int m = 0; m < 2; m++) {
                mma_bf16(acc[m][j], ah[m], bh0, bh1);
                mma_bf16(acc[m][j], al[m], bh0, bh1);
                mma_bf16(acc[m][j], ah[m], bl0, bl1);
            }
        }
    }
}

// fill Wh/Wl transposed from row-major W[k][n] (scalar LDG, 4B-safe)
__device__ __forceinline__ void fill_w_split(unsigned* Wh, unsigned* Wl,
                                             const float* __restrict__ W, int tid) {
    #pragma unroll
    for (int i = 0; i < 32; i++) {
        int idx = tid + (i << 8);        // 0..8191
        int n  = idx & 127;
        int kw = idx >> 7;               // 0..63
        float w0 = __ldg(W + (2 * kw) * DD + n);
        float w1 = __ldg(W + (2 * kw + 1) * DD + n);
        float l0, l1;
        float h0 = split_hi(w0, l0);
        float h1 = split_hi(w1, l1);
        Wh[n * KW + kw] = pack_bf16(h0, h1);
        Wl[n * KW + kw] = pack_bf16(l0, l1);
    }
}

// ---------------- edge_index dtype sniffer ----------------
__global__ void detect_idx_kernel(const unsigned int* ei32, int E_) {
    __shared__ int ok;
    if (threadIdx.x == 0) ok = 1;
    __syncthreads();
    if (E_ > 0) {
        long long stride = (long long)E_ / 256;
        if (stride < 1) stride = 1;
        long long i = (long long)threadIdx.x * stride;
        if (i < E_) {
            unsigned int hi = ei32[2 * i + 1];
            if (hi != 0) ok = 0;
        }
    }
    __syncthreads();
    if (threadIdx.x == 0) g_is64 = ok;
}

// smem word layout (unsigned): Ah[64*KW] | Al[64*KW] | Wh[128*KW] | Wl[128*KW] | tail
#define SM_AH 0
#define SM_AL (64 * KW)
#define SM_WH (128 * KW)
#define SM_WL (128 * KW + 128 * KW)          // == 2*64*KW + 128*KW
#define SM_TAIL (2 * 64 * KW + 2 * 128 * KW) // floats after the 4 tile arrays

// ---------------- fused node precompute: h, delta, xf ----------------
__global__ void __launch_bounds__(256, 2) node_pre(
    const float* __restrict__ x,
    const float* __restrict__ Wh1, const float* __restrict__ bh1,
    const float* __restrict__ Wh2, const float* __restrict__ bh2,
    const float* __restrict__ Wf1, const float* __restrict__ bf1,
    int n)
{
    extern __shared__ float sm[];
    unsigned* Ah = (unsigned*)sm;
    unsigned* Al = Ah + 64 * KW;
    unsigned* Wh = Al + 64 * KW;
    unsigned* Wl = Wh + 128 * KW;
    float* wh2s  = sm + SM_TAIL;         // 384
    float* b1s   = wh2s + 384;           // 128
    float* b2s   = b1s + 128;            // 128
    float* dpart = b2s + 128;            // 192
    const int tid  = threadIdx.x;
    const int row0 = blockIdx.x * 64;

    // A fill: x tile -> packed bf16 h/l (x is d_in[0], 16B-aligned)
    {
        const int row = tid >> 2;
        const int cb  = (tid & 3) << 5;   // k start (32 k per thread)
        int grow = row0 + row; if (grow >= n) grow = n - 1;
        #pragma unroll
        for (int i = 0; i < 8; i++) {
            int k = cb + (i << 2);
            float4 v = *(const float4*)(x + (size_t)grow * DD + k);
            float lx, ly, lz, lw;
            float hx = split_hi(v.x, lx), hy = split_hi(v.y, ly);
            float hz = split_hi(v.z, lz), hw = split_hi(v.w, lw);
            Ah[row * KW + (k >> 1)]     = pack_bf16(hx, hy);
            Ah[row * KW + (k >> 1) + 1] = pack_bf16(hz, hw);
            Al[row * KW + (k >> 1)]     = pack_bf16(lx, ly);
            Al[row * KW + (k >> 1) + 1] = pack_bf16(lz, lw);
        }
    }
    fill_w_split(Wh, Wl, Wh1, tid);
    if (tid < 192) {
        wh2s[tid]       = __ldg(Wh2 + tid);
        wh2s[tid + 192] = __ldg(Wh2 + tid + 192);
        dpart[tid] = 0.f;
    }
    if (tid < 128) {
        b1s[tid] = __ldg(bh1 + tid);
        b2s[tid] = __ldg(bf1 + tid);
    }
    __syncthreads();

    const int wid  = tid >> 5, lane = tid & 31;
    const int gid  = lane >> 2, tig = lane & 3;
    const int rw   = (wid & 1) * 32;
    const int cw   = (wid >> 1) * 32;

    // ---- GEMM1: h = leaky(x @ Wh1 + bh1) -> delta head ----
    float acc[2][4][4];
    gemm_warp(Ah, Al, Wh, Wl, rw, cw, lane, acc);

    {
        float d[2][2][3];
        #pragma unroll
        for (int m = 0; m < 2; m++)
            #pragma unroll
            for (int rh = 0; rh < 2; rh++)
                #pragma unroll
                for (int c = 0; c < 3; c++) d[m][rh][c] = 0.f;

        #pragma unroll
        for (int m = 0; m < 2; m++)
            #pragma unroll
            for (int j = 0; j < 4; j++)
                #pragma unroll
                for (int r = 0; r < 4; r++) {
                    int col = cw + 8 * j + 2 * tig + (r & 1);
                    int rh  = r >> 1;
                    float h = lrelu(acc[m][j][r] + b1s[col]);
                    const float* w2 = wh2s + col * 3;
                    d[m][rh][0] = fmaf(h, w2[0], d[m][rh][0]);
                    d[m][rh][1] = fmaf(h, w2[1], d[m][rh][1]);
                    d[m][rh][2] = fmaf(h, w2[2], d[m][rh][2]);
                }
        #pragma unroll
        for (int m = 0; m < 2; m++)
            #pragma unroll
            for (int rh = 0; rh < 2; rh++) {
                int lrow = rw + 16 * m + 8 * rh + gid;
                atomicAdd(&dpart[lrow * 3 + 0], d[m][rh][0]);
                atomicAdd(&dpart[lrow * 3 + 1], d[m][rh][1]);
                atomicAdd(&dpart[lrow * 3 + 2], d[m][rh][2]);
            }
    }
    __syncthreads();

    if (tid < 192) {
        int lrow = tid / 3, c = tid - lrow * 3;
        int grow = row0 + lrow;
        if (grow < n)
            g_delta[(size_t)grow * 3 + c] = tanhf(dpart[tid] + __ldg(bh2 + c));
    }
    __syncthreads();

    // refill W tiles with Wf1 rows 3..130
    fill_w_split(Wh, Wl, Wf1 + 3 * DD, tid);
    __syncthreads();

    // ---- GEMM2: xf = x @ Wf1[3:] + bf1 ----
    gemm_warp(Ah, Al, Wh, Wl, rw, cw, lane, acc);
    #pragma unroll
    for (int m = 0; m < 2; m++)
        #pragma unroll
        for (int j = 0; j < 4; j++)
            #pragma unroll
            for (int rh = 0; rh < 2; rh++) {
                int row  = rw + 16 * m + 8 * rh + gid;
                int col  = cw + 8 * j + 2 * tig;
                int grow = row0 + row;
                float2 v;
                v.x = acc[m][j][2 * rh + 0] + b2s[col];
                v.y = acc[m][j][2 * rh + 1] + b2s[col + 1];
                *(float2*)(g_xf + (size_t)grow * DD + col) = v;
            }
}

// ---------------- edge kernel: warp per 4 edges (unchanged from R11) ----------------
__global__ void __launch_bounds__(256) edge_kernel(
    const void* __restrict__ ei_raw, const float* __restrict__ pos,
    const float* __restrict__ Wf1, int E_)
{
    __shared__ float w[3 * DD];
    if (threadIdx.x < 128) {
        w[threadIdx.x]       = __ldg(Wf1 + threadIdx.x);
        w[128 + threadIdx.x] = __ldg(Wf1 + DD + threadIdx.x);
        w[256 + threadIdx.x] = __ldg(Wf1 + 2 * DD + threadIdx.x);
    }
    __syncthreads();

    const int lane = threadIdx.x & 31;
    const int c = lane << 2;
    float w0x = w[c], w0y = w[c+1], w0z = w[c+2], w0w = w[c+3];
    float w1x = w[128+c], w1y = w[128+c+1], w1z = w[128+c+2], w1w = w[128+c+3];
    float w2x = w[256+c], w2y = w[256+c+1], w2z = w[256+c+2], w2w = w[256+c+3];

    const int is64 = g_is64;
    int eBase = ((blockIdx.x << 3) + (threadIdx.x >> 5)) << 2;

    #pragma unroll
    for (int t = 0; t < 4; t++) {
        int e = eBase + t;
        if (e >= E_) break;

        int src, dst;
        if (is64) {
            const long long* ei = (const long long*)ei_raw;
            src = (int)__ldg(ei + e);
            dst = (int)__ldg(ei + (size_t)E_ + e);
        } else {
            const int* ei = (const int*)ei_raw;
            src = __ldg(ei + e);
            dst = __ldg(ei + (size_t)E_ + e);
        }

        float rv = 0.f;
        if (lane < 3)
            rv = __ldg(pos + src * 3 + lane) - __ldg(pos + dst * 3 + lane)
               + g_delta[dst * 3 + lane];
        float r0 = __shfl_sync(0xffffffffu, rv, 0);
        float r1 = __shfl_sync(0xffffffffu, rv, 1);
        float r2 = __shfl_sync(0xffffffffu, rv, 2);

        float4 xv = *(const float4*)(g_xf + (size_t)src * DD + c);
        float4 m;
        m.x = lrelu(fmaf(r0, w0x, fmaf(r1, w1x, fmaf(r2, w2x, xv.x))));
        m.y = lrelu(fmaf(r0, w0y, fmaf(r1, w1y, fmaf(r2, w2y, xv.y))));
        m.z = lrelu(fmaf(r0, w0z, fmaf(r1, w1z, fmaf(r2, w2z, xv.z))));
        m.w = lrelu(fmaf(r0, w0w, fmaf(r1, w1w, fmaf(r2, w2w, xv.w))));

        red_add_v4(g_aggr + (size_t)dst * DD + c, m);
    }
}

// ---------------- fused node post: out = x + leaky(aggr@Wg1+bg1)@Wg2 + bg2 ----------------
__global__ void __launch_bounds__(256, 2) node_post(
    const float* __restrict__ x,
    const float* __restrict__ Wg1, const float* __restrict__ bg1,
    const float* __restrict__ Wg2, const float* __restrict__ bg2,
    float* __restrict__ out, int n)
{
    extern __shared__ float sm[];
    unsigned* Ah = (unsigned*)sm;
    unsigned* Al = Ah + 64 * KW;
    unsigned* Wh = Al + 64 * KW;
    unsigned* Wl = Wh + 128 * KW;
    float* b1s = sm + SM_TAIL;
    float* b2s = b1s + 128;
    const int tid  = threadIdx.x;
    const int row0 = blockIdx.x * 64;

    // A fill from g_aggr (aligned device array)
    {
        const int row = tid >> 2;
        const int cb  = (tid & 3) << 5;
        int grow = row0 + row; if (grow >= n) grow = n - 1;
        #pragma unroll
        for (int i = 0; i < 8; i++) {
            int k = cb + (i << 2);
            float4 v = *(const float4*)(g_aggr + (size_t)grow * DD + k);
            float lx, ly, lz, lw;
            float hx = split_hi(v.x, lx), hy = split_hi(v.y, ly);
            float hz = split_hi(v.z, lz), hw = split_hi(v.w, lw);
            Ah[row * KW + (k >> 1)]     = pack_bf16(hx, hy);
            Ah[row * KW + (k >> 1) + 1] = pack_bf16(hz, hw);
            Al[row * KW + (k >> 1)]     = pack_bf16(lx, ly);
            Al[row * KW + (k >> 1) + 1] = pack_bf16(lz, lw);
        }
    }
    fill_w_split(Wh, Wl, Wg1, tid);
    if (tid < 128) {
        b1s[tid] = __ldg(bg1 + tid);
        b2s[tid] = __ldg(bg2 + tid);
    }
    __syncthreads();

    const int wid  = tid >> 5, lane = tid & 31;
    const int gid  = lane >> 2, tig = lane & 3;
    const int rw   = (wid & 1) * 32;
    const int cw   = (wid >> 1) * 32;

    float acc[2][4][4];
    gemm_warp(Ah, Al, Wh, Wl, rw, cw, lane, acc);
    __syncthreads();   // all warps done reading A/W tiles

    // t = leaky(acc + bg1) re-split into Ah/Al (each thread owns col pairs -> one word)
    #pragma unroll
    for (int m = 0; m < 2; m++)
        #pragma unroll
        for (int j = 0; j < 4; j++)
            #pragma unroll
            for (int rh = 0; rh < 2; rh++) {
                int row = rw + 16 * m + 8 * rh + gid;
                int col = cw + 8 * j + 2 * tig;
                float t0 = lrelu(acc[m][j][2 * rh + 0] + b1s[col]);
                float t1 = lrelu(acc[m][j][2 * rh + 1] + b1s[col + 1]);
                float l0, l1;
                float h0 = split_hi(t0, l0);
                float h1 = split_hi(t1, l1);
                int w = row * KW + (col >> 1);
                Ah[w] = pack_bf16(h0, h1);
                Al[w] = pack_bf16(l0, l1);
            }
    fill_w_split(Wh, Wl, Wg2, tid);
    __syncthreads();

    gemm_warp(Ah, Al, Wh, Wl, rw, cw, lane, acc);
    #pragma unroll
    for (int m = 0; m < 2; m++)
        #pragma unroll
        for (int j = 0; j < 4; j++)
            #pragma unroll
            for (int rh = 0; rh < 2; rh++) {
                int row  = rw + 16 * m + 8 * rh + gid;
                int col  = cw + 8 * j + 2 * tig;
                int grow = row0 + row;
                float2 xv = *(const float2*)(x + (size_t)grow * DD + col);
                float2 o;
                o.x = xv.x + acc[m][j][2 * rh + 0] + b2s[col];
                o.y = xv.y + acc[m][j][2 * rh + 1] + b2s[col + 1];
                *(float2*)(out + (size_t)grow * DD + col) = o;
            }
}

// ---------------- launch ----------------
extern "C" void kernel_launch(void* const* d_in, const int* in_sizes, int n_in,
                              void* d_out, int out_size)
{
    const float* x   = (const float*)d_in[0];
    const float* pos = (const float*)d_in[1];
    const void*  ei  = d_in[2];
    const float* Wh1 = (const float*)d_in[3];
    const float* bh1 = (const float*)d_in[4];
    const float* Wh2 = (const float*)d_in[5];
    const float* bh2 = (const float*)d_in[6];
    const float* Wf1 = (const float*)d_in[7];
    const float* bf1 = (const float*)d_in[8];
    const float* Wg1 = (const float*)d_in[9];
    const float* bg1 = (const float*)d_in[10];
    const float* Wg2 = (const float*)d_in[11];
    const float* bg2 = (const float*)d_in[12];
    float* out = (float*)d_out;

    const int n  = in_sizes[0] / DD;
    const int E_ = in_sizes[2] / 2;

    const int PRE_SMEM  = (SM_TAIL + 384 + 128 + 128 + 192) * (int)sizeof(float);
    const int POST_SMEM = (SM_TAIL + 128 + 128) * (int)sizeof(float);
    cudaFuncSetAttribute(node_pre,  cudaFuncAttributeMaxDynamicSharedMemorySize, PRE_SMEM);
    cudaFuncSetAttribute(node_post, cudaFuncAttributeMaxDynamicSharedMemorySize, POST_SMEM);

    void* aggrPtr = nullptr;
    cudaGetSymbolAddress(&aggrPtr, g_aggr);
    cudaMemsetAsync(aggrPtr, 0, (size_t)n * DD * sizeof(float));

    detect_idx_kernel<<<1, 256>>>((const unsigned int*)ei, E_);

    const int gridN = (n + 63) / 64;
    node_pre<<<gridN, 256, PRE_SMEM>>>(x, Wh1, bh1, Wh2, bh2, Wf1, bf1, n);
    const int edgeBlocks = (E_ + 31) / 32;
    edge_kernel<<<edgeBlocks, 256>>>(ei, pos, Wf1, E_);
    node_post<<<gridN, 256, POST_SMEM>>>(x, Wg1, bg1, Wg2, bg2, out, n);
}

// round 16
// speedup vs baseline: 1.2807x; 1.2807x over previous
#include <cuda_runtime.h>

#define DD 128
#define NMAX 40000
#define ASR 132   // A tile stride (floats): float4-aligned rows, conflict-free frags
#define BSR 132   // W tile stride

// ---------------- device scratch (no allocs allowed), 16B-aligned ----------------
__device__ __align__(16) float g_delta[(size_t)NMAX * 3];
__device__ __align__(16) float g_xf[(size_t)NMAX * DD];
__device__ __align__(16) float g_aggr[(size_t)NMAX * DD];
__device__ __align__(16) float g_wh[4][DD * DD];   // tf32-hi of Wh1, Wf1x, Wg1, Wg2
__device__ __align__(16) float g_wl[4][DD * DD];   // tf32-lo residuals
__device__ int   g_is64;

__device__ __forceinline__ float lrelu(float v) { return v >= 0.f ? v : 0.01f * v; }

__device__ __forceinline__ void red_add_v4(float* addr, float4 v) {
    asm volatile("red.global.add.v4.f32 [%0], {%1,%2,%3,%4};"
                 :: "l"(addr), "f"(v.x), "f"(v.y), "f"(v.z), "f"(v.w) : "memory");
}

// ---------------- tf32 mma helpers ----------------
__device__ __forceinline__ unsigned cvt_tf32(float v) {
    unsigned r; asm("cvt.rna.tf32.f32 %0, %1;" : "=r"(r) : "f"(v)); return r;
}
__device__ __forceinline__ void mma_tf32(float d[4], const unsigned a[4],
                                         unsigned b0, unsigned b1) {
    asm("mma.sync.aligned.m16n8k8.row.col.f32.tf32.tf32.f32 "
        "{%0,%1,%2,%3}, {%4,%5,%6,%7}, {%8,%9}, {%0,%1,%2,%3};"
        : "+f"(d[0]), "+f"(d[1]), "+f"(d[2]), "+f"(d[3])
        : "r"(a[0]), "r"(a[1]), "r"(a[2]), "r"(a[3]), "r"(b0), "r"(b1));
}

// ---------------- one-time weight pre-split (tf32 hi/lo as fp32 bit patterns) ----------------
__global__ void split_weights_kernel(const float* __restrict__ Wh1,
                                     const float* __restrict__ Wf1,
                                     const float* __restrict__ Wg1,
                                     const float* __restrict__ Wg2) {
    int i = blockIdx.x * 256 + threadIdx.x;   // 0..16383, grid = 64
    const float* srcs[4] = {Wh1, Wf1 + 3 * DD, Wg1, Wg2};
    #pragma unroll
    for (int m = 0; m < 4; m++) {
        float v = __ldg(srcs[m] + i);
        unsigned h = cvt_tf32(v);
        float l = v - __uint_as_float(h);
        g_wh[m][i] = __uint_as_float(h);
        g_wl[m][i] = __uint_as_float(cvt_tf32(l));
    }
}

// copy one 64-k half of pre-split weights into smem tiles [64][BSR] (pure float4 copy)
__device__ __forceinline__ void fill_half(float* WsH, float* WsL,
                                          const float* __restrict__ GH,
                                          const float* __restrict__ GL, int tid) {
    #pragma unroll
    for (int i = 0; i < 8; i++) {
        int q  = tid + (i << 8);        // quad index 0..2047 (2048 quads = 64x128 words)
        int k  = q >> 5;                // 0..63
        int nq = (q & 31) << 2;         // 0,4,..,124
        *(float4*)(WsH + k * BSR + nq) = *(const float4*)(GH + (q << 2));
        *(float4*)(WsL + k * BSR + nq) = *(const float4*)(GL + (q << 2));
    }
}

// Warp-tiled 3-pass tf32 GEMM over one 64-k half.
// As: [64][ASR] fp32 (split on the fly); WsH/WsL: [64][BSR] pre-split tf32 bits.
// acc[m][j][r]: row = rw+16m+gid+8*(r>>1), col = cw+8j+2*tig+(r&1)
__device__ __forceinline__ void gemm_half(const float* __restrict__ As,
                                          const float* __restrict__ WsH,
                                          const float* __restrict__ WsL,
                                          int rw, int cw, int lane, int aBase,
                                          float acc[2][4][4]) {
    const int gid = lane >> 2, tig = lane & 3;
    #pragma unroll 2
    for (int k0 = 0; k0 < 64; k0 += 8) {
        unsigned ah[2][4], al[2][4];
        #pragma unroll
        for (int m = 0; m < 2; m++) {
            const float* ap = As + (rw + 16 * m + gid) * ASR + aBase + k0 + tig;
            float a0 = ap[0];
            float a1 = ap[8 * ASR];
            float a2 = ap[4];
            float a3 = ap[8 * ASR + 4];
            ah[m][0] = cvt_tf32(a0); al[m][0] = cvt_tf32(a0 - __uint_as_float(ah[m][0]));
            ah[m][1] = cvt_tf32(a1); al[m][1] = cvt_tf32(a1 - __uint_as_float(ah[m][1]));
            ah[m][2] = cvt_tf32(a2); al[m][2] = cvt_tf32(a2 - __uint_as_float(ah[m][2]));
            ah[m][3] = cvt_tf32(a3); al[m][3] = cvt_tf32(a3 - __uint_as_float(ah[m][3]));
        }
        #pragma unroll
        for (int j = 0; j < 4; j++) {
            const float* bhp = WsH + (k0 + tig) * BSR + cw + 8 * j + gid;
            const float* blp = WsL + (k0 + tig) * BSR + cw + 8 * j + gid;
            unsigned bh0 = __float_as_uint(bhp[0]);
            unsigned bh1 = __float_as_uint(bhp[4 * BSR]);
            unsigned bl0 = __float_as_uint(blp[0]);
            unsigned bl1 = __float_as_uint(blp[4 * BSR]);
            #pragma unroll
            for (int m = 0; m < 2; m++) {
                mma_tf32(acc[m][j], ah[m], bh0, bh1);
                mma_tf32(acc[m][j], al[m], bh0, bh1);
                mma_tf32(acc[m][j], ah[m], bl0, bl1);
            }
        }
    }
}

__device__ __forceinline__ void zero_acc(float acc[2][4][4]) {
    #pragma unroll
    for (int m = 0; m < 2; m++)
        #pragma unroll
        for (int j = 0; j < 4; j++)
            #pragma unroll
            for (int r = 0; r < 4; r++) acc[m][j][r] = 0.f;
}

// full GEMM = two half-k phases against pre-split weight matrix wsel
__device__ __forceinline__ void gemm_full(const float* As, float* WsH, float* WsL,
                                          int wsel, int tid, int rw, int cw, int lane,
                                          float acc[2][4][4]) {
    zero_acc(acc);
    fill_half(WsH, WsL, g_wh[wsel], g_wl[wsel], tid);
    __syncthreads();
    gemm_half(As, WsH, WsL, rw, cw, lane, 0, acc);
    __syncthreads();
    fill_half(WsH, WsL, g_wh[wsel] + 64 * DD, g_wl[wsel] + 64 * DD, tid);
    __syncthreads();
    gemm_half(As, WsH, WsL, rw, cw, lane, 64, acc);
}

// ---------------- edge_index dtype sniffer ----------------
__global__ void detect_idx_kernel(const unsigned int* ei32, int E_) {
    __shared__ int ok;
    if (threadIdx.x == 0) ok = 1;
    __syncthreads();
    if (E_ > 0) {
        long long stride = (long long)E_ / 256;
        if (stride < 1) stride = 1;
        long long i = (long long)threadIdx.x * stride;
        if (i < E_) {
            unsigned int hi = ei32[2 * i + 1];
            if (hi != 0) ok = 0;
        }
    }
    __syncthreads();
    if (threadIdx.x == 0) g_is64 = ok;
}

// ---------------- fused node precompute: h, delta, xf ----------------
// smem: As[64][ASR] | WsH[64][BSR] | WsL[64][BSR] | wh2s[384] | b1s[128] | b2s[128] | dpart[192]
__global__ void __launch_bounds__(256, 2) node_pre(
    const float* __restrict__ x,
    const float* __restrict__ bh1,
    const float* __restrict__ Wh2, const float* __restrict__ bh2,
    const float* __restrict__ bf1,
    int n)
{
    extern __shared__ float sm[];
    float* As    = sm;
    float* WsH   = sm + 64 * ASR;
    float* WsL   = WsH + 64 * BSR;
    float* wh2s  = WsL + 64 * BSR;
    float* b1s   = wh2s + 384;
    float* b2s   = b1s + 128;
    float* dpart = b2s + 128;
    const int tid  = threadIdx.x;
    const int row0 = blockIdx.x * 64;

    // A fill (x = d_in[0], 16B-aligned)
    {
        const int row = tid >> 2;
        const int cb  = (tid & 3) << 2;
        int grow = row0 + row; if (grow >= n) grow = n - 1;
        #pragma unroll
        for (int i = 0; i < 8; i++) {
            int col = cb + (i << 4);
            *(float4*)(As + row * ASR + col) = *(const float4*)(x + (size_t)grow * DD + col);
        }
    }
    if (tid < 192) {
        wh2s[tid]       = __ldg(Wh2 + tid);
        wh2s[tid + 192] = __ldg(Wh2 + tid + 192);
        dpart[tid] = 0.f;
    }
    if (tid < 128) {
        b1s[tid] = __ldg(bh1 + tid);
        b2s[tid] = __ldg(bf1 + tid);
    }

    const int wid  = tid >> 5, lane = tid & 31;
    const int gid  = lane >> 2, tig = lane & 3;
    const int rw   = (wid & 1) * 32;
    const int cw   = (wid >> 1) * 32;

    // ---- GEMM1: h = leaky(x @ Wh1 + bh1) -> delta head ----
    float acc[2][4][4];
    gemm_full(As, WsH, WsL, 0, tid, rw, cw, lane, acc);

    {
        float d[2][2][3];
        #pragma unroll
        for (int m = 0; m < 2; m++)
            #pragma unroll
            for (int rh = 0; rh < 2; rh++)
                #pragma unroll
                for (int c = 0; c < 3; c++) d[m][rh][c] = 0.f;

        #pragma unroll
        for (int m = 0; m < 2; m++)
            #pragma unroll
            for (int j = 0; j < 4; j++)
                #pragma unroll
                for (int r = 0; r < 4; r++) {
                    int col = cw + 8 * j + 2 * tig + (r & 1);
                    int rh  = r >> 1;
                    float h = lrelu(acc[m][j][r] + b1s[col]);
                    const float* w2 = wh2s + col * 3;
                    d[m][rh][0] = fmaf(h, w2[0], d[m][rh][0]);
                    d[m][rh][1] = fmaf(h, w2[1], d[m][rh][1]);
                    d[m][rh][2] = fmaf(h, w2[2], d[m][rh][2]);
                }
        #pragma unroll
        for (int m = 0; m < 2; m++)
            #pragma unroll
            for (int rh = 0; rh < 2; rh++) {
                int lrow = rw + 16 * m + 8 * rh + gid;
                atomicAdd(&dpart[lrow * 3 + 0], d[m][rh][0]);
                atomicAdd(&dpart[lrow * 3 + 1], d[m][rh][1]);
                atomicAdd(&dpart[lrow * 3 + 2], d[m][rh][2]);
            }
    }
    __syncthreads();

    if (tid < 192) {
        int lrow = tid / 3, c = tid - lrow * 3;
        int grow = row0 + lrow;
        if (grow < n)
            g_delta[(size_t)grow * 3 + c] = tanhf(dpart[tid] + __ldg(bh2 + c));
    }
    __syncthreads();

    // ---- GEMM2: xf = x @ Wf1[3:] + bf1 ----
    gemm_full(As, WsH, WsL, 1, tid, rw, cw, lane, acc);
    #pragma unroll
    for (int m = 0; m < 2; m++)
        #pragma unroll
        for (int j = 0; j < 4; j++)
            #pragma unroll
            for (int rh = 0; rh < 2; rh++) {
                int row  = rw + 16 * m + 8 * rh + gid;
                int col  = cw + 8 * j + 2 * tig;
                int grow = row0 + row;
                float2 v;
                v.x = acc[m][j][2 * rh + 0] + b2s[col];
                v.y = acc[m][j][2 * rh + 1] + b2s[col + 1];
                *(float2*)(g_xf + (size_t)grow * DD + col) = v;
            }
}

// ---------------- edge kernel: warp per 4 edges (unchanged from R11) ----------------
__global__ void __launch_bounds__(256) edge_kernel(
    const void* __restrict__ ei_raw, const float* __restrict__ pos,
    const float* __restrict__ Wf1, int E_)
{
    __shared__ float w[3 * DD];
    if (threadIdx.x < 128) {
        w[threadIdx.x]       = __ldg(Wf1 + threadIdx.x);
        w[128 + threadIdx.x] = __ldg(Wf1 + DD + threadIdx.x);
        w[256 + threadIdx.x] = __ldg(Wf1 + 2 * DD + threadIdx.x);
    }
    __syncthreads();

    const int lane = threadIdx.x & 31;
    const int c = lane << 2;
    float w0x = w[c], w0y = w[c+1], w0z = w[c+2], w0w = w[c+3];
    float w1x = w[128+c], w1y = w[128+c+1], w1z = w[128+c+2], w1w = w[128+c+3];
    float w2x = w[256+c], w2y = w[256+c+1], w2z = w[256+c+2], w2w = w[256+c+3];

    const int is64 = g_is64;
    int eBase = ((blockIdx.x << 3) + (threadIdx.x >> 5)) << 2;

    #pragma unroll
    for (int t = 0; t < 4; t++) {
        int e = eBase + t;
        if (e >= E_) break;

        int src, dst;
        if (is64) {
            const long long* ei = (const long long*)ei_raw;
            src = (int)__ldg(ei + e);
            dst = (int)__ldg(ei + (size_t)E_ + e);
        } else {
            const int* ei = (const int*)ei_raw;
            src = __ldg(ei + e);
            dst = __ldg(ei + (size_t)E_ + e);
        }

        float rv = 0.f;
        if (lane < 3)
            rv = __ldg(pos + src * 3 + lane) - __ldg(pos + dst * 3 + lane)
               + g_delta[dst * 3 + lane];
        float r0 = __shfl_sync(0xffffffffu, rv, 0);
        float r1 = __shfl_sync(0xffffffffu, rv, 1);
        float r2 = __shfl_sync(0xffffffffu, rv, 2);

        float4 xv = *(const float4*)(g_xf + (size_t)src * DD + c);
        float4 m;
        m.x = lrelu(fmaf(r0, w0x, fmaf(r1, w1x, fmaf(r2, w2x, xv.x))));
        m.y = lrelu(fmaf(r0, w0y, fmaf(r1, w1y, fmaf(r2, w2y, xv.y))));
        m.z = lrelu(fmaf(r0, w0z, fmaf(r1, w1z, fmaf(r2, w2z, xv.z))));
        m.w = lrelu(fmaf(r0, w0w, fmaf(r1, w1w, fmaf(r2, w2w, xv.w))));

        red_add_v4(g_aggr + (size_t)dst * DD + c, m);
    }
}

// ---------------- fused node post: out = x + leaky(aggr@Wg1+bg1)@Wg2 + bg2 ----------------
// smem: As[64][ASR] | WsH[64][BSR] | WsL[64][BSR] | b1s[128] | b2s[128]
__global__ void __launch_bounds__(256, 2) node_post(
    const float* __restrict__ x,
    const float* __restrict__ bg1,
    const float* __restrict__ bg2,
    float* __restrict__ out, int n)
{
    extern __shared__ float sm[];
    float* As  = sm;
    float* WsH = sm + 64 * ASR;
    float* WsL = WsH + 64 * BSR;
    float* b1s = WsL + 64 * BSR;
    float* b2s = b1s + 128;
    const int tid  = threadIdx.x;
    const int row0 = blockIdx.x * 64;

    {
        const int row = tid >> 2;
        const int cb  = (tid & 3) << 2;
        int grow = row0 + row; if (grow >= n) grow = n - 1;
        #pragma unroll
        for (int i = 0; i < 8; i++) {
            int col = cb + (i << 4);
            *(float4*)(As + row * ASR + col) =
                *(const float4*)(g_aggr + (size_t)grow * DD + col);
        }
    }
    if (tid < 128) {
        b1s[tid] = __ldg(bg1 + tid);
        b2s[tid] = __ldg(bg2 + tid);
    }

    const int wid  = tid >> 5, lane = tid & 31;
    const int gid  = lane >> 2, tig = lane & 3;
    const int rw   = (wid & 1) * 32;
    const int cw   = (wid >> 1) * 32;

    float acc[2][4][4];
    gemm_full(As, WsH, WsL, 2, tid, rw, cw, lane, acc);
    __syncthreads();   // all warps done reading As before overwrite

    // t = leaky(acc + bg1) written back into As
    #pragma unroll
    for (int m = 0; m < 2; m++)
        #pragma unroll
        for (int j = 0; j < 4; j++)
            #pragma unroll
            for (int rh = 0; rh < 2; rh++) {
                int row = rw + 16 * m + 8 * rh + gid;
                int col = cw + 8 * j + 2 * tig;
                As[row * ASR + col]     = lrelu(acc[m][j][2 * rh + 0] + b1s[col]);
                As[row * ASR + col + 1] = lrelu(acc[m][j][2 * rh + 1] + b1s[col + 1]);
            }
    __syncthreads();

    gemm_full(As, WsH, WsL, 3, tid, rw, cw, lane, acc);
    #pragma unroll
    for (int m = 0; m < 2; m++)
        #pragma unroll
        for (int j = 0; j < 4; j++)
            #pragma unroll
            for (int rh = 0; rh < 2; rh++) {
                int row  = rw + 16 * m + 8 * rh + gid;
                int col  = cw + 8 * j + 2 * tig;
                int grow = row0 + row;
                float2 xv = *(const float2*)(x + (size_t)grow * DD + col);
                float2 o;
                o.x = xv.x + acc[m][j][2 * rh + 0] + b2s[col];
                o.y = xv.y + acc[m][j][2 * rh + 1] + b2s[col + 1];
                *(float2*)(out + (size_t)grow * DD + col) = o;
            }
}

// ---------------- launch ----------------
extern "C" void kernel_launch(void* const* d_in, const int* in_sizes, int n_in,
                              void* d_out, int out_size)
{
    const float* x   = (const float*)d_in[0];
    const float* pos = (const float*)d_in[1];
    const void*  ei  = d_in[2];
    const float* Wh1 = (const float*)d_in[3];
    const float* bh1 = (const float*)d_in[4];
    const float* Wh2 = (const float*)d_in[5];
    const float* bh2 = (const float*)d_in[6];
    const float* Wf1 = (const float*)d_in[7];
    const float* bf1 = (const float*)d_in[8];
    const float* Wg1 = (const float*)d_in[9];
    const float* bg1 = (const float*)d_in[10];
    const float* Wg2 = (const float*)d_in[11];
    const float* bg2 = (const float*)d_in[12];
    float* out = (float*)d_out;

    const int n  = in_sizes[0] / DD;
    const int E_ = in_sizes[2] / 2;

    const int PRE_SMEM  = (64 * ASR + 2 * 64 * BSR + 384 + 128 + 128 + 192) * (int)sizeof(float);
    const int POST_SMEM = (64 * ASR + 2 * 64 * BSR + 128 + 128) * (int)sizeof(float);
    cudaFuncSetAttribute(node_pre,  cudaFuncAttributeMaxDynamicSharedMemorySize, PRE_SMEM);
    cudaFuncSetAttribute(node_post, cudaFuncAttributeMaxDynamicSharedMemorySize, POST_SMEM);

    void* aggrPtr = nullptr;
    cudaGetSymbolAddress(&aggrPtr, g_aggr);
    cudaMemsetAsync(aggrPtr, 0, (size_t)n * DD * sizeof(float));

    detect_idx_kernel<<<1, 256>>>((const unsigned int*)ei, E_);
    split_weights_kernel<<<64, 256>>>(Wh1, Wf1, Wg1, Wg2);

    const int gridN = (n + 63) / 64;
    node_pre<<<gridN, 256, PRE_SMEM>>>(x, bh1, Wh2, bh2, bf1, n);
    const int edgeBlocks = (E_ + 31) / 32;
    edge_kernel<<<edgeBlocks, 256>>>(ei, pos, Wf1, E_);
    node_post<<<gridN, 256, POST_SMEM>>>(x, bg1, bg2, out, n);
}